// round 3
// baseline (speedup 1.0000x reference)
#include <cuda_runtime.h>
#include <stdint.h>

// out[i, :] = W[idx[i], :]   idx:[32768] int32, W:[8192,512] f32, out:[32768,512] f32
// Flat gather over float4 lanes. Shapes are static and exactly tile-divisible:
// 32768 rows * 128 float4/row = 4,194,304 vectors; 256 thr * 4 = 1024 vec/CTA; grid = 4096.
// Each thread front-batches 4 independent LDG.128 (MLP=4), then 4 STG.128.

static constexpr int E_DIM    = 512;
static constexpr int VEC_ROW  = E_DIM / 4;   // 128 float4 per row
static constexpr int THREADS  = 256;
static constexpr int UNROLL   = 4;

__global__ void __launch_bounds__(THREADS, 8)
gather_rows_kernel(const int* __restrict__ idx,
                   const float4* __restrict__ table,   // [8192, 128] float4
                   float4* __restrict__ out)           // [32768, 128] float4
{
    const int base = (blockIdx.x * THREADS) * UNROLL + threadIdx.x;

    float4 v[UNROLL];

    // Front-batched independent loads: idx (L1/L2-hot) then gathered table row slice.
    #pragma unroll
    for (int u = 0; u < UNROLL; ++u) {
        const int g   = base + u * THREADS;
        const int row = g >> 7;              // / 128
        const int t   = g & (VEC_ROW - 1);   // % 128
        const int src = __ldg(&idx[row]);
        v[u] = __ldg(&table[(size_t)src * VEC_ROW + t]);
    }

    #pragma unroll
    for (int u = 0; u < UNROLL; ++u) {
        out[base + u * THREADS] = v[u];
    }
}

extern "C" void kernel_launch(void* const* d_in, const int* in_sizes, int n_in,
                              void* d_out, int out_size)
{
    const int*    idx   = (const int*)d_in[0];      // min_encoding_indices [32768]
    const float4* table = (const float4*)d_in[1];   // embedding_weight [8192,512]
    float4*       out   = (float4*)d_out;           // [32,1024,512] f32

    const int n_rows    = in_sizes[0];              // 32768
    const int total_vec = n_rows * VEC_ROW;         // 4,194,304
    const int per_cta   = THREADS * UNROLL;         // 1024
    const int grid      = total_vec / per_cta;      // 4096 (exact)

    gather_rows_kernel<<<grid, THREADS>>>(idx, table, out);
}